// round 7
// baseline (speedup 1.0000x reference)
#include <cuda_runtime.h>
#include <cuda_bf16.h>
#include <cstdint>

#define BB 8192
#define LL 256
#define BPWARP 8                     // batches per warp (4 lanes each)
#define GRAN 11                      // float4 granules per batch row per group (9 data + 2 pad)
#define ROWB (GRAN * 16)             // 176 B
#define BUF_BYTES (BPWARP * ROWB)    // 1408 B
#define NBUF 4

static __device__ __forceinline__ unsigned long long pk2(float lo, float hi) {
    unsigned long long r; asm("mov.b64 %0, {%1,%2};" : "=l"(r) : "f"(lo), "f"(hi)); return r;
}
static __device__ __forceinline__ void upk2(float& lo, float& hi, unsigned long long v) {
    asm("mov.b64 {%0,%1}, %2;" : "=f"(lo), "=f"(hi) : "l"(v));
}
static __device__ __forceinline__ unsigned long long fma2_(unsigned long long a, unsigned long long b, unsigned long long c) {
    unsigned long long d; asm("fma.rn.f32x2 %0, %1, %2, %3;" : "=l"(d) : "l"(a), "l"(b), "l"(c)); return d;
}
static __device__ __forceinline__ unsigned long long mul2_(unsigned long long a, unsigned long long b) {
    unsigned long long d; asm("mul.rn.f32x2 %0, %1, %2;" : "=l"(d) : "l"(a), "l"(b)); return d;
}
static __device__ __forceinline__ unsigned int smem_u32(const void* p) {
    unsigned int a; asm("{ .reg .u64 t; cvta.to.shared.u64 t, %1; cvt.u32.u64 %0, t; }" : "=r"(a) : "l"(p)); return a;
}
static __device__ __forceinline__ void cpasync16(unsigned int dst, const void* src) {
    asm volatile("cp.async.ca.shared.global [%0], [%1], 16;" :: "r"(dst), "l"(src));
}
static __device__ __forceinline__ float lds_f(unsigned int a) {
    float v; asm volatile("ld.shared.f32 %0, [%1];" : "=f"(v) : "r"(a)); return v;
}
#define CP_COMMIT() asm volatile("cp.async.commit_group;" ::: "memory")
#define CP_WAIT(n)  asm volatile("cp.async.wait_group %0;" :: "n"(n) : "memory")

__global__ __launch_bounds__(32) void crf_fwd_kernel(
    const float* __restrict__ inputs,   // [B, L, 9]
    const int*   __restrict__ path,     // [B, L]
    const float* __restrict__ tran,     // [9, 9]
    const float* __restrict__ initv,    // [9]
    float* __restrict__ out)            // [B]
{
    __shared__ float s_tran[81];
    __shared__ float s_init[9];
    __shared__ __align__(16) char xbuf[NBUF * BUF_BYTES];

    const int lane = threadIdx.x;
    const int quad = lane >> 2;          // 0..7  : batch within warp
    const int sub  = lane & 3;           // 0..3  : role within quad
    const int b    = blockIdx.x * BPWARP + quad;
    const unsigned FULL = 0xFFFFFFFFu;

    for (int i = lane; i < 81; i += 32) s_tran[i] = tran[i];
    if (lane < 9) s_init[lane] = initv[lane];
    __syncwarp();

    const unsigned int sbase = smem_u32(xbuf);

    // zero the 2 pad granules of every row in every buffer (64 stores of 16B)
    #pragma unroll
    for (int j = 0; j < 2; ++j) {
        int idx = lane + 32 * j;         // 0..63
        int buf = idx >> 4, rem = idx & 15;
        int row = rem >> 1, gr = 9 + (rem & 1);
        unsigned int a = sbase + (unsigned int)(buf * BUF_BYTES + row * ROWB + gr * 16);
        asm volatile("st.shared.v4.f32 [%0], {%1,%2,%3,%4};"
                     :: "r"(a), "f"(0.f), "f"(0.f), "f"(0.f), "f"(0.f));
    }

    // ---- per-lane permuted output order (states padded to 12; 9..11 dummy) ----
    // OrderP[sub]: [keep3 | send-in-round2 (3) | send-in-round1 (6, = xor1-partner's first 6)]
    // sub0: 0 1 2 3 4 5 | 6 7 8 9 10 11
    // sub1: 6 7 8 9 10 11 | 0 1 2 3 4 5
    // sub2: 3 4 5 0 1 2 | 9 10 11 6 7 8
    // sub3: 9 10 11 6 7 8 | 3 4 5 0 1 2
    int ord[12];
    {
        int lo6  = (sub & 1) ? 6 : 0;         // my kept-6 base
        int swap = (sub & 2) ? 3 : 0;         // round-2 swap within kept-6
        #pragma unroll
        for (int k = 0; k < 6; ++k) ord[k] = lo6 + ((k + swap) % 6 < 3 ? (k + swap) % 6 : (k + swap) % 6);
        // kept-6 order: [lo6+swap, lo6+swap+1, lo6+swap+2, lo6+(swap^3)...] -- build explicitly:
        ord[0] = lo6 + swap + 0; ord[1] = lo6 + swap + 1; ord[2] = lo6 + swap + 2;
        ord[3] = lo6 + (3 - swap) + 0; ord[4] = lo6 + (3 - swap) + 1; ord[5] = lo6 + (3 - swap) + 2;
        // sent-6 = xor1 partner's kept-6 order:
        int plo6  = 6 - lo6;
        int pswap = swap;                      // partner (xor1) has same bit1
        ord[6] = plo6 + pswap + 0; ord[7] = plo6 + pswap + 1; ord[8] = plo6 + pswap + 2;
        ord[9] = plo6 + (3 - pswap) + 0; ord[10] = plo6 + (3 - pswap) + 1; ord[11] = plo6 + (3 - pswap) + 2;
    }
    const int myb = ord[0];                    // my 3 states: myb, myb+1, myb+2 (sub3: 9..11 dummy)

    // E registers: Ep[m][c] = pk2(E2[s][ord[2c]], E2[s][ord[2c+1]]), s = myb+m
    unsigned long long Ep[3][6];
    #pragma unroll
    for (int m = 0; m < 3; ++m) {
        int s = myb + m;
        #pragma unroll
        for (int c = 0; c < 6; ++c) {
            int ja = ord[2*c], jb = ord[2*c+1];
            float ea = (s < 9 && ja < 9) ? __expf(s_tran[s * 9 + ja]) : 0.f;
            float eb = (s < 9 && jb < 9) ? __expf(s_tran[s * 9 + jb]) : 0.f;
            Ep[m][c] = pk2(ea, eb);
        }
    }
    float myini[3];
    #pragma unroll
    for (int k = 0; k < 3; ++k) myini[k] = (myb + k < 9) ? s_init[myb + k] : -1e30f;
    const unsigned int xoff = (unsigned int)((myb < 9 ? myb : 0) * 4);   // byte offset of my states in a step row

    // ---- cp.async descriptors: 8 rows x 9 granules = 72 float4 per group ----
    const char* gsrc[3];
    unsigned int sdst[3];
    #pragma unroll
    for (int i = 0; i < 3; ++i) {
        int f = lane + 32 * i;
        int ff = (f < 72) ? f : 0;
        int bi = ff / 9, oi = ff - bi * 9;
        gsrc[i] = (const char*)inputs + (size_t)(blockIdx.x * BPWARP + bi) * (LL * 9 * 4) + oi * 16;
        sdst[i] = sbase + (unsigned int)(bi * GRAN + oi) * 16;
    }
    const bool c2 = (lane < 8);    // slot 2 validity

    auto issue = [&](int g) {
        unsigned int boff = (unsigned int)(g & 3) * BUF_BYTES;
        cpasync16(sdst[0] + boff, gsrc[0] + g * 144);
        cpasync16(sdst[1] + boff, gsrc[1] + g * 144);
        if (c2) cpasync16(sdst[2] + boff, gsrc[2] + g * 144);
        CP_COMMIT();
    };

    issue(0); issue(1); issue(2);

    const unsigned int myrowbase = sbase + (unsigned int)quad * ROWB;

    const int4* pb4 = (const int4*)(path + (size_t)b * LL);

    float p0, p1, p2;
    float C = 0.f, emit = 0.f, tracc = 0.f;
    int ptp;

    // one scan step
    auto step = [&](unsigned int rowa, int tt, int pt) {
        unsigned int xb = rowa + (unsigned int)tt * 36u;
        float x0 = lds_f(xb + xoff);
        float x1 = lds_f(xb + xoff + 4);
        float x2 = lds_f(xb + xoff + 8);
        float e0 = __expf(x0), e1 = __expf(x1), e2 = __expf(x2);

        unsigned long long q, A0, A1, A2, A3, A4, A5;
        q = pk2(p0, p0);
        A0 = mul2_(q, Ep[0][0]); A1 = mul2_(q, Ep[0][1]); A2 = mul2_(q, Ep[0][2]);
        A3 = mul2_(q, Ep[0][3]); A4 = mul2_(q, Ep[0][4]); A5 = mul2_(q, Ep[0][5]);
        q = pk2(p1, p1);
        A0 = fma2_(q, Ep[1][0], A0); A1 = fma2_(q, Ep[1][1], A1); A2 = fma2_(q, Ep[1][2], A2);
        A3 = fma2_(q, Ep[1][3], A3); A4 = fma2_(q, Ep[1][4], A4); A5 = fma2_(q, Ep[1][5], A5);
        q = pk2(p2, p2);
        A0 = fma2_(q, Ep[2][0], A0); A1 = fma2_(q, Ep[2][1], A1); A2 = fma2_(q, Ep[2][2], A2);
        A3 = fma2_(q, Ep[2][3], A3); A4 = fma2_(q, Ep[2][4], A4); A5 = fma2_(q, Ep[2][5], A5);

        float P0, P1, P2, P3, P4, P5, P6, P7, P8, P9, P10, P11;
        upk2(P0, P1, A0); upk2(P2, P3, A1); upk2(P4, P5, A2);
        upk2(P6, P7, A3); upk2(P8, P9, A4); upk2(P10, P11, A5);

        // butterfly round 1 (xor 1): send P6..P11, keep P0..P5
        float K0 = P0 + __shfl_xor_sync(FULL, P6, 1);
        float K1 = P1 + __shfl_xor_sync(FULL, P7, 1);
        float K2 = P2 + __shfl_xor_sync(FULL, P8, 1);
        float K3 = P3 + __shfl_xor_sync(FULL, P9, 1);
        float K4 = P4 + __shfl_xor_sync(FULL, P10, 1);
        float K5 = P5 + __shfl_xor_sync(FULL, P11, 1);
        // round 2 (xor 2): send K3..K5, keep K0..K2
        float J0 = K0 + __shfl_xor_sync(FULL, K3, 2);
        float J1 = K1 + __shfl_xor_sync(FULL, K4, 2);
        float J2 = K2 + __shfl_xor_sync(FULL, K5, 2);

        p0 = J0 * e0; p1 = J1 * e1; p2 = J2 * e2;

        emit  += lds_f(xb + (unsigned int)(pt * 4));
        tracc += s_tran[ptp * 9 + pt];
        ptp = pt;
    };

    auto renorm = [&]() {
        float loc = (p0 + p1) + p2;
        loc += __shfl_xor_sync(FULL, loc, 1);
        loc += __shfl_xor_sync(FULL, loc, 2);
        C += __logf(loc);
        float inv = __fdividef(1.f, loc);
        p0 *= inv; p1 *= inv; p2 *= inv;
    };

    // ---- group 0: t=0 init + steps 1..3 ----
    CP_WAIT(2); __syncwarp();
    int4 pg = pb4[0];
    unsigned int rowa = myrowbase;       // buffer 0
    p0 = __expf(myini[0] + lds_f(rowa + xoff));
    p1 = __expf(myini[1] + lds_f(rowa + xoff + 4));
    p2 = __expf(myini[2] + lds_f(rowa + xoff + 8));
    ptp = pg.x;
    emit = lds_f(rowa + (unsigned int)(pg.x * 4));
    const float initterm = s_init[pg.x];
    step(rowa, 1, pg.y);
    step(rowa, 2, pg.z);
    step(rowa, 3, pg.w);
    __syncwarp();
    issue(3);

    // ---- main loop: groups 1..60 ----
    #pragma unroll 1
    for (int g = 1; g <= 60; ++g) {
        CP_WAIT(2); __syncwarp();
        int4 pgg = pb4[g];
        unsigned int ra = myrowbase + (unsigned int)(g & 3) * BUF_BYTES;
        step(ra, 0, pgg.x);
        step(ra, 1, pgg.y);
        step(ra, 2, pgg.z);
        step(ra, 3, pgg.w);
        __syncwarp();
        issue(g + 3);
        if (g & 1) renorm();             // every 8 steps
    }

    // ---- tail: groups 61..63 ----
    CP_WAIT(0); __syncwarp();
    #pragma unroll 1
    for (int g = 61; g <= 63; ++g) {
        int4 pgg = pb4[g];
        unsigned int ra = myrowbase + (unsigned int)(g & 3) * BUF_BYTES;
        step(ra, 0, pgg.x);
        step(ra, 1, pgg.y);
        step(ra, 2, pgg.z);
        step(ra, 3, pgg.w);
        if (g == 61) renorm();
    }

    float loc = (p0 + p1) + p2;
    loc += __shfl_xor_sync(FULL, loc, 1);
    loc += __shfl_xor_sync(FULL, loc, 2);
    float logZ = C + __logf(loc);
    if (sub == 0) {
        out[b] = logZ - (emit + initterm + tracc);
    }
}

extern "C" void kernel_launch(void* const* d_in, const int* in_sizes, int n_in,
                              void* d_out, int out_size) {
    (void)in_sizes; (void)n_in; (void)out_size;
    const float* inputs = (const float*)d_in[0];
    const int*   path   = (const int*)d_in[1];
    const float* tran   = (const float*)d_in[2];
    const float* initv  = (const float*)d_in[3];
    float* out = (float*)d_out;

    crf_fwd_kernel<<<BB / BPWARP, 32>>>(inputs, path, tran, initv, out);
}

// round 9
// speedup vs baseline: 1.8946x; 1.8946x over previous
#include <cuda_runtime.h>
#include <cuda_bf16.h>
#include <cstdint>

#define BB 8192
#define LL 256
#define BPB 16                       // batches per block (2 warps: fwd + bwd)
#define GRAN 11                      // float4 granules per batch row per group
#define ROWB (GRAN * 16)             // 176 B
#define BUF_BYTES (BPB * ROWB)       // 2816 B
#define NBUF 4

static __device__ __forceinline__ unsigned long long pk2(float lo, float hi) {
    unsigned long long r; asm("mov.b64 %0, {%1,%2};" : "=l"(r) : "f"(lo), "f"(hi)); return r;
}
static __device__ __forceinline__ void upk2(float& lo, float& hi, unsigned long long v) {
    asm("mov.b64 {%0,%1}, %2;" : "=f"(lo), "=f"(hi) : "l"(v));
}
static __device__ __forceinline__ unsigned long long fma2_(unsigned long long a, unsigned long long b, unsigned long long c) {
    unsigned long long d; asm("fma.rn.f32x2 %0, %1, %2, %3;" : "=l"(d) : "l"(a), "l"(b), "l"(c)); return d;
}
static __device__ __forceinline__ unsigned long long mul2_(unsigned long long a, unsigned long long b) {
    unsigned long long d; asm("mul.rn.f32x2 %0, %1, %2;" : "=l"(d) : "l"(a), "l"(b)); return d;
}
static __device__ __forceinline__ unsigned long long add2_(unsigned long long a, unsigned long long b) {
    unsigned long long d; asm("add.rn.f32x2 %0, %1, %2;" : "=l"(d) : "l"(a), "l"(b)); return d;
}
static __device__ __forceinline__ unsigned int smem_u32(const void* p) {
    unsigned int a; asm("{ .reg .u64 t; cvta.to.shared.u64 t, %1; cvt.u32.u64 %0, t; }" : "=r"(a) : "l"(p)); return a;
}
static __device__ __forceinline__ void cpasync16(unsigned int dst, const void* src) {
    asm volatile("cp.async.ca.shared.global [%0], [%1], 16;" :: "r"(dst), "l"(src));
}
static __device__ __forceinline__ float lds_f(unsigned int a) {
    float v; asm volatile("ld.shared.f32 %0, [%1];" : "=f"(v) : "r"(a)); return v;
}
#define CP_COMMIT() asm volatile("cp.async.commit_group;" ::: "memory")
#define CP_WAIT(n)  asm volatile("cp.async.wait_group %0;" :: "n"(n) : "memory")

__global__ __launch_bounds__(64) void crf_fwd_kernel(
    const float* __restrict__ inputs,   // [B, L, 9]
    const int*   __restrict__ path,     // [B, L]
    const float* __restrict__ tran,     // [9, 9]
    const float* __restrict__ initv,    // [9]
    float* __restrict__ out)            // [B]
{
    __shared__ float s_tran[81];
    __shared__ float s_init[9];
    __shared__ __align__(16) char xbuf[2 * NBUF * BUF_BYTES];
    __shared__ float fin[BPB][26];

    const int tid  = threadIdx.x;
    const int w    = tid >> 5;           // 0 = forward (t 0..127), 1 = backward (t 255..128)
    const int lane = tid & 31;
    const int pair = lane >> 1;
    const int sub  = lane & 1;
    const int b    = blockIdx.x * BPB + pair;
    const unsigned FULL = 0xFFFFFFFFu;

    for (int i = tid; i < 81; i += 64) s_tran[i] = tran[i];
    if (tid < 9) s_init[tid] = initv[tid];
    __syncthreads();

    const unsigned int sWbase = smem_u32(xbuf) + (unsigned int)w * (NBUF * BUF_BYTES);

    // zero pad granules (9,10) of every row in this warp's 4 buffers
    #pragma unroll
    for (int j = 0; j < 4; ++j) {
        int idx = lane + 32 * j;           // 0..127
        int buf = idx >> 5, rem = idx & 31;
        int row = rem >> 1, gr = 9 + (rem & 1);
        unsigned int a = sWbase + (unsigned int)(buf * BUF_BYTES + row * ROWB + gr * 16);
        asm volatile("st.shared.v4.f32 [%0], {%1,%2,%3,%4};"
                     :: "r"(a), "f"(0.f), "f"(0.f), "f"(0.f), "f"(0.f));
    }

    const int ownbase = sub * 5;
    const int rembase = 5 - sub * 5;

    // E packs. Forward (w=0): out j = ownbase+k, src i; entry E[src][out].
    // Backward (w=1): out i = ownbase+k, src j; entry E[out][src]  (transpose).
    unsigned long long EoA[5], EoB[5], ErA[5], ErB[5];
    float EoS[5], ErS[5];
    #pragma unroll
    for (int m = 0; m < 5; ++m) {
        int so = ownbase + m, sr = rembase + m;
        float eo[5], er[5];
        #pragma unroll
        for (int k = 0; k < 5; ++k) {
            int o = ownbase + k;
            eo[k] = (so < 9 && o < 9) ? __expf(w ? s_tran[o * 9 + so] : s_tran[so * 9 + o]) : 0.f;
            er[k] = (sr < 9 && o < 9) ? __expf(w ? s_tran[o * 9 + sr] : s_tran[sr * 9 + o]) : 0.f;
        }
        EoA[m] = pk2(eo[0], eo[1]); EoB[m] = pk2(eo[2], eo[3]); EoS[m] = eo[4];
        ErA[m] = pk2(er[0], er[1]); ErB[m] = pk2(er[2], er[3]); ErS[m] = er[4];
    }

    // cp.async descriptors: 16 rows x 9 granules = 144 float4 per group
    const char* gsrc[5];
    unsigned int sdst[5];
    bool cval[5];
    #pragma unroll
    for (int i = 0; i < 5; ++i) {
        int f4 = lane + 32 * i;
        bool vv = (f4 < 144);
        int ff = vv ? f4 : 0;
        int bi = ff / 9, oi = ff - bi * 9;
        gsrc[i] = (const char*)inputs + (size_t)(blockIdx.x * BPB + bi) * (LL * 9 * 4) + oi * 16;
        sdst[i] = sWbase + (unsigned int)(bi * GRAN + oi) * 16;
        cval[i] = vv;
    }

    auto issue = [&](int g) {
        unsigned int boff = (unsigned int)(g & 3) * BUF_BYTES;
        #pragma unroll
        for (int i = 0; i < 5; ++i)
            if (cval[i]) cpasync16(sdst[i] + boff, gsrc[i] + g * 144);
        CP_COMMIT();
    };

    const unsigned int myrowbase = sWbase + (unsigned int)pair * ROWB;
    float f[40];
    auto loadx = [&](int g) {
        unsigned int a = myrowbase + (unsigned int)(g & 3) * BUF_BYTES;
        #pragma unroll
        for (int i = 0; i < 10; ++i)
            asm volatile("ld.shared.v4.f32 {%0,%1,%2,%3}, [%4];"
                         : "=f"(f[4*i]), "=f"(f[4*i+1]), "=f"(f[4*i+2]), "=f"(f[4*i+3])
                         : "r"(a + i * 16));
    };
    #define XG(t,k) (sub ? f[9*(t)+5+(k)] : f[9*(t)+(k)])

    const int4* pb4 = (const int4*)(path + (size_t)b * LL);

    float p0, p1, p2, p3, p4;          // forward alpha / backward state (own 5 states)
    float C = 0.f, emit = 0.f, tracc = 0.f;
    int ptp;                           // fwd: previous path state; bwd: successor path state

    auto matvec = [&](float y0, float y1, float y2, float y3, float y4,
                      float& n0, float& n1, float& n2, float& n3, float& n4) {
        float r0 = __shfl_xor_sync(FULL, y0, 1);
        float r1 = __shfl_xor_sync(FULL, y1, 1);
        float r2 = __shfl_xor_sync(FULL, y2, 1);
        float r3 = __shfl_xor_sync(FULL, y3, 1);
        float r4 = __shfl_xor_sync(FULL, y4, 1);
        unsigned long long q, A0, A1, B0, B1;
        float a4, b4;
        q = pk2(y0, y0); A0 = mul2_(q, EoA[0]); A1 = mul2_(q, EoB[0]); a4 = y0 * EoS[0];
        q = pk2(y1, y1); A0 = fma2_(q, EoA[1], A0); A1 = fma2_(q, EoB[1], A1); a4 = fmaf(y1, EoS[1], a4);
        q = pk2(y2, y2); A0 = fma2_(q, EoA[2], A0); A1 = fma2_(q, EoB[2], A1); a4 = fmaf(y2, EoS[2], a4);
        q = pk2(y3, y3); A0 = fma2_(q, EoA[3], A0); A1 = fma2_(q, EoB[3], A1); a4 = fmaf(y3, EoS[3], a4);
        q = pk2(y4, y4); A0 = fma2_(q, EoA[4], A0); A1 = fma2_(q, EoB[4], A1); a4 = fmaf(y4, EoS[4], a4);
        q = pk2(r0, r0); B0 = mul2_(q, ErA[0]); B1 = mul2_(q, ErB[0]); b4 = r0 * ErS[0];
        q = pk2(r1, r1); B0 = fma2_(q, ErA[1], B0); B1 = fma2_(q, ErB[1], B1); b4 = fmaf(r1, ErS[1], b4);
        q = pk2(r2, r2); B0 = fma2_(q, ErA[2], B0); B1 = fma2_(q, ErB[2], B1); b4 = fmaf(r2, ErS[2], b4);
        q = pk2(r3, r3); B0 = fma2_(q, ErA[3], B0); B1 = fma2_(q, ErB[3], B1); b4 = fmaf(r3, ErS[3], b4);
        q = pk2(r4, r4); B0 = fma2_(q, ErA[4], B0); B1 = fma2_(q, ErB[4], B1); b4 = fmaf(r4, ErS[4], b4);
        A0 = add2_(A0, B0); A1 = add2_(A1, B1); a4 += b4;
        upk2(n0, n1, A0); upk2(n2, n3, A1); n4 = a4;
    };

    auto renorm = [&]() {
        float loc = ((p0 + p1) + (p2 + p3)) + p4;
        float s = loc + __shfl_xor_sync(FULL, loc, 1);
        C += __logf(s);
        float inv = __fdividef(1.f, s);
        p0 *= inv; p1 *= inv; p2 *= inv; p3 *= inv; p4 *= inv;
    };

    if (w == 0) {
        // ================= forward half: t = 0 .. 127, groups 0..31 =================
        auto step = [&](float x0, float x1, float x2, float x3, float x4,
                        int pt, unsigned int rowa, int tt) {
            float e0 = __expf(x0), e1 = __expf(x1), e2 = __expf(x2);
            float e3 = __expf(x3), e4 = __expf(x4);
            float n0, n1, n2, n3, n4;
            matvec(p0, p1, p2, p3, p4, n0, n1, n2, n3, n4);
            p0 = n0 * e0; p1 = n1 * e1; p2 = n2 * e2; p3 = n3 * e3; p4 = n4 * e4;
            emit  += lds_f(rowa + (unsigned int)((tt * 9 + pt) * 4));
            tracc += s_tran[ptp * 9 + pt];
            ptp = pt;
        };

        issue(0); issue(1); issue(2);
        CP_WAIT(2); __syncwarp();
        loadx(0);
        int4 pg = pb4[0];
        unsigned int rowa = myrowbase;
        float i0 = (ownbase + 0 < 9) ? s_init[ownbase + 0] : -1e30f;
        float i1 = (ownbase + 1 < 9) ? s_init[ownbase + 1] : -1e30f;
        float i2 = (ownbase + 2 < 9) ? s_init[ownbase + 2] : -1e30f;
        float i3 = (ownbase + 3 < 9) ? s_init[ownbase + 3] : -1e30f;
        float i4 = (ownbase + 4 < 9) ? s_init[ownbase + 4] : -1e30f;
        p0 = __expf(i0 + XG(0,0)); p1 = __expf(i1 + XG(0,1)); p2 = __expf(i2 + XG(0,2));
        p3 = __expf(i3 + XG(0,3)); p4 = __expf(i4 + XG(0,4));
        ptp = pg.x;
        emit = lds_f(rowa + (unsigned int)(pg.x * 4));
        const float initterm = s_init[pg.x];
        step(XG(1,0),XG(1,1),XG(1,2),XG(1,3),XG(1,4), pg.y, rowa, 1);
        step(XG(2,0),XG(2,1),XG(2,2),XG(2,3),XG(2,4), pg.z, rowa, 2);
        step(XG(3,0),XG(3,1),XG(3,2),XG(3,3),XG(3,4), pg.w, rowa, 3);
        __syncwarp();
        issue(3);

        #pragma unroll 1
        for (int g = 1; g <= 28; ++g) {
            CP_WAIT(2); __syncwarp();
            loadx(g);
            int4 pgg = pb4[g];
            unsigned int ra = myrowbase + (unsigned int)(g & 3) * BUF_BYTES;
            step(XG(0,0),XG(0,1),XG(0,2),XG(0,3),XG(0,4), pgg.x, ra, 0);
            step(XG(1,0),XG(1,1),XG(1,2),XG(1,3),XG(1,4), pgg.y, ra, 1);
            step(XG(2,0),XG(2,1),XG(2,2),XG(2,3),XG(2,4), pgg.z, ra, 2);
            step(XG(3,0),XG(3,1),XG(3,2),XG(3,3),XG(3,4), pgg.w, ra, 3);
            __syncwarp();
            issue(g + 3);
            if (g & 1) renorm();
        }
        CP_WAIT(0); __syncwarp();
        #pragma unroll 1
        for (int g = 29; g <= 31; ++g) {
            loadx(g);
            int4 pgg = pb4[g];
            unsigned int ra = myrowbase + (unsigned int)(g & 3) * BUF_BYTES;
            step(XG(0,0),XG(0,1),XG(0,2),XG(0,3),XG(0,4), pgg.x, ra, 0);
            step(XG(1,0),XG(1,1),XG(1,2),XG(1,3),XG(1,4), pgg.y, ra, 1);
            step(XG(2,0),XG(2,1),XG(2,2),XG(2,3),XG(2,4), pgg.z, ra, 2);
            step(XG(3,0),XG(3,1),XG(3,2),XG(3,3),XG(3,4), pgg.w, ra, 3);
            if (g == 29) renorm();
        }

        // publish: v (alpha_127), C, aggregate score, p127
        if (sub == 0) {
            fin[pair][0] = p0; fin[pair][1] = p1; fin[pair][2] = p2;
            fin[pair][3] = p3; fin[pair][4] = p4;
            fin[pair][9]  = C;
            fin[pair][10] = emit + initterm + tracc;
            fin[pair][11] = __int_as_float(ptp);
        } else {
            fin[pair][5] = p0; fin[pair][6] = p1; fin[pair][7] = p2; fin[pair][8] = p3;
        }
    } else {
        // ================= backward half: t = 255 .. 128, groups 63..32 =================
        // beta_{t-1} = E * (exp(x_t) .* beta_t); state p = E*(D_t ... ), see init
        auto bstep = [&](float x0, float x1, float x2, float x3, float x4,
                         int pt, unsigned int rowa, int tt) {
            float y0 = p0 * __expf(x0), y1 = p1 * __expf(x1), y2 = p2 * __expf(x2);
            float y3 = p3 * __expf(x3), y4 = p4 * __expf(x4);
            matvec(y0, y1, y2, y3, y4, p0, p1, p2, p3, p4);
            emit  += lds_f(rowa + (unsigned int)((tt * 9 + pt) * 4));
            tracc += s_tran[pt * 9 + ptp];
            ptp = pt;
        };

        issue(63); issue(62); issue(61);
        CP_WAIT(2); __syncwarp();
        loadx(63);
        int4 pg = pb4[63];
        unsigned int rowa = myrowbase + 3u * BUF_BYTES;   // 63 & 3 == 3
        // init: p = E * exp(x_255) = beta_254  (FIX: apply the E of the t=255 factor)
        p0 = (ownbase + 0 < 9) ? __expf(XG(3,0)) : 0.f;
        p1 = (ownbase + 1 < 9) ? __expf(XG(3,1)) : 0.f;
        p2 = (ownbase + 2 < 9) ? __expf(XG(3,2)) : 0.f;
        p3 = (ownbase + 3 < 9) ? __expf(XG(3,3)) : 0.f;
        p4 = (ownbase + 4 < 9) ? __expf(XG(3,4)) : 0.f;
        matvec(p0, p1, p2, p3, p4, p0, p1, p2, p3, p4);
        ptp = pg.w;
        emit = lds_f(rowa + (unsigned int)((3 * 9 + pg.w) * 4));
        bstep(XG(2,0),XG(2,1),XG(2,2),XG(2,3),XG(2,4), pg.z, rowa, 2);
        bstep(XG(1,0),XG(1,1),XG(1,2),XG(1,3),XG(1,4), pg.y, rowa, 1);
        bstep(XG(0,0),XG(0,1),XG(0,2),XG(0,3),XG(0,4), pg.x, rowa, 0);
        __syncwarp();
        issue(60);

        #pragma unroll 1
        for (int g = 62; g >= 35; --g) {
            CP_WAIT(2); __syncwarp();
            loadx(g);
            int4 pgg = pb4[g];
            unsigned int ra = myrowbase + (unsigned int)(g & 3) * BUF_BYTES;
            bstep(XG(3,0),XG(3,1),XG(3,2),XG(3,3),XG(3,4), pgg.w, ra, 3);
            bstep(XG(2,0),XG(2,1),XG(2,2),XG(2,3),XG(2,4), pgg.z, ra, 2);
            bstep(XG(1,0),XG(1,1),XG(1,2),XG(1,3),XG(1,4), pgg.y, ra, 1);
            bstep(XG(0,0),XG(0,1),XG(0,2),XG(0,3),XG(0,4), pgg.x, ra, 0);
            __syncwarp();
            issue(g - 3);
            if ((g & 1) == 0) renorm();
        }
        CP_WAIT(0); __syncwarp();
        #pragma unroll 1
        for (int g = 34; g >= 32; --g) {
            loadx(g);
            int4 pgg = pb4[g];
            unsigned int ra = myrowbase + (unsigned int)(g & 3) * BUF_BYTES;
            bstep(XG(3,0),XG(3,1),XG(3,2),XG(3,3),XG(3,4), pgg.w, ra, 3);
            bstep(XG(2,0),XG(2,1),XG(2,2),XG(2,3),XG(2,4), pgg.z, ra, 2);
            bstep(XG(1,0),XG(1,1),XG(1,2),XG(1,3),XG(1,4), pgg.y, ra, 1);
            bstep(XG(0,0),XG(0,1),XG(0,2),XG(0,3),XG(0,4), pgg.x, ra, 0);
            if (g == 34) renorm();
        }

        // publish: w (beta_127), C, aggregate score, p128
        if (sub == 0) {
            fin[pair][12] = p0; fin[pair][13] = p1; fin[pair][14] = p2;
            fin[pair][15] = p3; fin[pair][16] = p4;
            fin[pair][21] = C;
            fin[pair][22] = emit + tracc;
            fin[pair][23] = __int_as_float(ptp);
        } else {
            fin[pair][17] = p0; fin[pair][18] = p1; fin[pair][19] = p2; fin[pair][20] = p3;
        }
    }
    #undef XG

    __syncthreads();

    // combine: 16 lanes of warp 0 (sub == 0), one per batch
    if (w == 0 && sub == 0) {
        float dot = 0.f;
        #pragma unroll
        for (int i = 0; i < 9; ++i) dot = fmaf(fin[pair][i], fin[pair][12 + i], dot);
        float logZ = fin[pair][9] + fin[pair][21] + __logf(dot);
        int pa = __float_as_int(fin[pair][11]);
        int pb = __float_as_int(fin[pair][23]);
        float score = fin[pair][10] + fin[pair][22] + s_tran[pa * 9 + pb];
        out[b] = logZ - score;
    }
}

extern "C" void kernel_launch(void* const* d_in, const int* in_sizes, int n_in,
                              void* d_out, int out_size) {
    (void)in_sizes; (void)n_in; (void)out_size;
    const float* inputs = (const float*)d_in[0];
    const int*   path   = (const int*)d_in[1];
    const float* tran   = (const float*)d_in[2];
    const float* initv  = (const float*)d_in[3];
    float* out = (float*)d_out;

    crf_fwd_kernel<<<BB / BPB, 64>>>(inputs, path, tran, initv, out);
}

// round 10
// speedup vs baseline: 2.0554x; 1.0849x over previous
#include <cuda_runtime.h>
#include <cuda_bf16.h>
#include <cstdint>

#define BB 8192
#define LL 256
#define BPSET 16                     // batches per set (one fwd + one bwd warp)
#define SETS 2                       // sets per block -> 4 warps, all SMSPs used
#define BPBLK (BPSET * SETS)         // 32
#define GRAN 11
#define ROWB (GRAN * 16)             // 176 B
#define BUF_BYTES (BPSET * ROWB)     // 2816 B
#define NBUF 4

static __device__ __forceinline__ unsigned long long pk2(float lo, float hi) {
    unsigned long long r; asm("mov.b64 %0, {%1,%2};" : "=l"(r) : "f"(lo), "f"(hi)); return r;
}
static __device__ __forceinline__ void upk2(float& lo, float& hi, unsigned long long v) {
    asm("mov.b64 {%0,%1}, %2;" : "=f"(lo), "=f"(hi) : "l"(v));
}
static __device__ __forceinline__ unsigned long long fma2_(unsigned long long a, unsigned long long b, unsigned long long c) {
    unsigned long long d; asm("fma.rn.f32x2 %0, %1, %2, %3;" : "=l"(d) : "l"(a), "l"(b), "l"(c)); return d;
}
static __device__ __forceinline__ unsigned long long mul2_(unsigned long long a, unsigned long long b) {
    unsigned long long d; asm("mul.rn.f32x2 %0, %1, %2;" : "=l"(d) : "l"(a), "l"(b)); return d;
}
static __device__ __forceinline__ unsigned long long add2_(unsigned long long a, unsigned long long b) {
    unsigned long long d; asm("add.rn.f32x2 %0, %1, %2;" : "=l"(d) : "l"(a), "l"(b)); return d;
}
static __device__ __forceinline__ unsigned int smem_u32(const void* p) {
    unsigned int a; asm("{ .reg .u64 t; cvta.to.shared.u64 t, %1; cvt.u32.u64 %0, t; }" : "=r"(a) : "l"(p)); return a;
}
static __device__ __forceinline__ void cpasync16(unsigned int dst, const void* src) {
    asm volatile("cp.async.ca.shared.global [%0], [%1], 16;" :: "r"(dst), "l"(src));
}
static __device__ __forceinline__ float lds_f(unsigned int a) {
    float v; asm volatile("ld.shared.f32 %0, [%1];" : "=f"(v) : "r"(a)); return v;
}
#define CP_COMMIT() asm volatile("cp.async.commit_group;" ::: "memory")
#define CP_WAIT(n)  asm volatile("cp.async.wait_group %0;" :: "n"(n) : "memory")

__global__ __launch_bounds__(128) void crf_fwd_kernel(
    const float* __restrict__ inputs,   // [B, L, 9]
    const int*   __restrict__ path,     // [B, L]
    const float* __restrict__ tran,     // [9, 9]
    const float* __restrict__ initv,    // [9]
    float* __restrict__ out)            // [B]
{
    __shared__ float s_tran[81];
    __shared__ float s_init[9];
    __shared__ __align__(16) char xbuf[SETS * 2 * NBUF * BUF_BYTES];
    __shared__ float fin[SETS][BPSET][26];

    const int tid  = threadIdx.x;
    const int set  = tid >> 6;           // 0,1  : batch set within block
    const int w    = (tid >> 5) & 1;     // 0 = forward (t 0..127), 1 = backward (t 255..128)
    const int lane = tid & 31;
    const int pair = lane >> 1;
    const int sub  = lane & 1;
    const int b    = blockIdx.x * BPBLK + set * BPSET + pair;
    const unsigned FULL = 0xFFFFFFFFu;

    for (int i = tid; i < 81; i += 128) s_tran[i] = tran[i];
    if (tid < 9) s_init[tid] = initv[tid];
    __syncthreads();

    const unsigned int sWbase = smem_u32(xbuf)
        + (unsigned int)(set * 2 + w) * (NBUF * BUF_BYTES);

    // zero pad granules (9,10) of every row in this warp's 4 buffers
    #pragma unroll
    for (int j = 0; j < 4; ++j) {
        int idx = lane + 32 * j;           // 0..127
        int buf = idx >> 5, rem = idx & 31;
        int row = rem >> 1, gr = 9 + (rem & 1);
        unsigned int a = sWbase + (unsigned int)(buf * BUF_BYTES + row * ROWB + gr * 16);
        asm volatile("st.shared.v4.f32 [%0], {%1,%2,%3,%4};"
                     :: "r"(a), "f"(0.f), "f"(0.f), "f"(0.f), "f"(0.f));
    }

    const int ownbase = sub * 5;
    const int rembase = 5 - sub * 5;

    // E packs. Forward: entry E[src][out]. Backward: E[out][src] (transpose).
    unsigned long long EoA[5], EoB[5], ErA[5], ErB[5];
    float EoS[5], ErS[5];
    #pragma unroll
    for (int m = 0; m < 5; ++m) {
        int so = ownbase + m, sr = rembase + m;
        float eo[5], er[5];
        #pragma unroll
        for (int k = 0; k < 5; ++k) {
            int o = ownbase + k;
            eo[k] = (so < 9 && o < 9) ? __expf(w ? s_tran[o * 9 + so] : s_tran[so * 9 + o]) : 0.f;
            er[k] = (sr < 9 && o < 9) ? __expf(w ? s_tran[o * 9 + sr] : s_tran[sr * 9 + o]) : 0.f;
        }
        EoA[m] = pk2(eo[0], eo[1]); EoB[m] = pk2(eo[2], eo[3]); EoS[m] = eo[4];
        ErA[m] = pk2(er[0], er[1]); ErB[m] = pk2(er[2], er[3]); ErS[m] = er[4];
    }

    // cp.async descriptors: 16 rows x 9 granules = 144 float4 per group
    const char* gsrc[5];
    unsigned int sdst[5];
    bool cval[5];
    #pragma unroll
    for (int i = 0; i < 5; ++i) {
        int f4 = lane + 32 * i;
        bool vv = (f4 < 144);
        int ff = vv ? f4 : 0;
        int bi = ff / 9, oi = ff - bi * 9;
        gsrc[i] = (const char*)inputs
                + (size_t)(blockIdx.x * BPBLK + set * BPSET + bi) * (LL * 9 * 4) + oi * 16;
        sdst[i] = sWbase + (unsigned int)(bi * GRAN + oi) * 16;
        cval[i] = vv;
    }

    auto issue = [&](int g) {
        unsigned int boff = (unsigned int)(g & 3) * BUF_BYTES;
        #pragma unroll
        for (int i = 0; i < 5; ++i)
            if (cval[i]) cpasync16(sdst[i] + boff, gsrc[i] + g * 144);
        CP_COMMIT();
    };

    const unsigned int myrowbase = sWbase + (unsigned int)pair * ROWB;
    float f[40];
    auto loadx = [&](int g) {
        unsigned int a = myrowbase + (unsigned int)(g & 3) * BUF_BYTES;
        #pragma unroll
        for (int i = 0; i < 10; ++i)
            asm volatile("ld.shared.v4.f32 {%0,%1,%2,%3}, [%4];"
                         : "=f"(f[4*i]), "=f"(f[4*i+1]), "=f"(f[4*i+2]), "=f"(f[4*i+3])
                         : "r"(a + i * 16));
    };
    #define XG(t,k) (sub ? f[9*(t)+5+(k)] : f[9*(t)+(k)])

    const int4* pb4 = (const int4*)(path + (size_t)b * LL);

    float p0, p1, p2, p3, p4;
    float C = 0.f, emit = 0.f, tracc = 0.f;
    int ptp;

    auto matvec = [&](float y0, float y1, float y2, float y3, float y4,
                      float& n0, float& n1, float& n2, float& n3, float& n4) {
        float r0 = __shfl_xor_sync(FULL, y0, 1);
        float r1 = __shfl_xor_sync(FULL, y1, 1);
        float r2 = __shfl_xor_sync(FULL, y2, 1);
        float r3 = __shfl_xor_sync(FULL, y3, 1);
        float r4 = __shfl_xor_sync(FULL, y4, 1);
        unsigned long long q, A0, A1, B0, B1;
        float a4, b4;
        q = pk2(y0, y0); A0 = mul2_(q, EoA[0]); A1 = mul2_(q, EoB[0]); a4 = y0 * EoS[0];
        q = pk2(y1, y1); A0 = fma2_(q, EoA[1], A0); A1 = fma2_(q, EoB[1], A1); a4 = fmaf(y1, EoS[1], a4);
        q = pk2(y2, y2); A0 = fma2_(q, EoA[2], A0); A1 = fma2_(q, EoB[2], A1); a4 = fmaf(y2, EoS[2], a4);
        q = pk2(y3, y3); A0 = fma2_(q, EoA[3], A0); A1 = fma2_(q, EoB[3], A1); a4 = fmaf(y3, EoS[3], a4);
        q = pk2(y4, y4); A0 = fma2_(q, EoA[4], A0); A1 = fma2_(q, EoB[4], A1); a4 = fmaf(y4, EoS[4], a4);
        q = pk2(r0, r0); B0 = mul2_(q, ErA[0]); B1 = mul2_(q, ErB[0]); b4 = r0 * ErS[0];
        q = pk2(r1, r1); B0 = fma2_(q, ErA[1], B0); B1 = fma2_(q, ErB[1], B1); b4 = fmaf(r1, ErS[1], b4);
        q = pk2(r2, r2); B0 = fma2_(q, ErA[2], B0); B1 = fma2_(q, ErB[2], B1); b4 = fmaf(r2, ErS[2], b4);
        q = pk2(r3, r3); B0 = fma2_(q, ErA[3], B0); B1 = fma2_(q, ErB[3], B1); b4 = fmaf(r3, ErS[3], b4);
        q = pk2(r4, r4); B0 = fma2_(q, ErA[4], B0); B1 = fma2_(q, ErB[4], B1); b4 = fmaf(r4, ErS[4], b4);
        A0 = add2_(A0, B0); A1 = add2_(A1, B1); a4 += b4;
        upk2(n0, n1, A0); upk2(n2, n3, A1); n4 = a4;
    };

    auto renorm = [&]() {
        float loc = ((p0 + p1) + (p2 + p3)) + p4;
        float s = loc + __shfl_xor_sync(FULL, loc, 1);
        C += __logf(s);
        float inv = __fdividef(1.f, s);
        p0 *= inv; p1 *= inv; p2 *= inv; p3 *= inv; p4 *= inv;
    };

    if (w == 0) {
        // ===== forward half: t = 0 .. 127, groups 0..31 =====
        auto step = [&](float x0, float x1, float x2, float x3, float x4,
                        int pt, unsigned int rowa, int tt) {
            float e0 = __expf(x0), e1 = __expf(x1), e2 = __expf(x2);
            float e3 = __expf(x3), e4 = __expf(x4);
            float n0, n1, n2, n3, n4;
            matvec(p0, p1, p2, p3, p4, n0, n1, n2, n3, n4);
            p0 = n0 * e0; p1 = n1 * e1; p2 = n2 * e2; p3 = n3 * e3; p4 = n4 * e4;
            emit  += lds_f(rowa + (unsigned int)((tt * 9 + pt) * 4));
            tracc += s_tran[ptp * 9 + pt];
            ptp = pt;
        };

        issue(0); issue(1); issue(2);
        CP_WAIT(2); __syncwarp();
        loadx(0);
        int4 pg = pb4[0];
        unsigned int rowa = myrowbase;
        float i0 = (ownbase + 0 < 9) ? s_init[ownbase + 0] : -1e30f;
        float i1 = (ownbase + 1 < 9) ? s_init[ownbase + 1] : -1e30f;
        float i2 = (ownbase + 2 < 9) ? s_init[ownbase + 2] : -1e30f;
        float i3 = (ownbase + 3 < 9) ? s_init[ownbase + 3] : -1e30f;
        float i4 = (ownbase + 4 < 9) ? s_init[ownbase + 4] : -1e30f;
        p0 = __expf(i0 + XG(0,0)); p1 = __expf(i1 + XG(0,1)); p2 = __expf(i2 + XG(0,2));
        p3 = __expf(i3 + XG(0,3)); p4 = __expf(i4 + XG(0,4));
        ptp = pg.x;
        emit = lds_f(rowa + (unsigned int)(pg.x * 4));
        const float initterm = s_init[pg.x];
        step(XG(1,0),XG(1,1),XG(1,2),XG(1,3),XG(1,4), pg.y, rowa, 1);
        step(XG(2,0),XG(2,1),XG(2,2),XG(2,3),XG(2,4), pg.z, rowa, 2);
        step(XG(3,0),XG(3,1),XG(3,2),XG(3,3),XG(3,4), pg.w, rowa, 3);
        __syncwarp();
        issue(3);

        #pragma unroll 1
        for (int g = 1; g <= 28; ++g) {
            CP_WAIT(2); __syncwarp();
            loadx(g);
            int4 pgg = pb4[g];
            unsigned int ra = myrowbase + (unsigned int)(g & 3) * BUF_BYTES;
            step(XG(0,0),XG(0,1),XG(0,2),XG(0,3),XG(0,4), pgg.x, ra, 0);
            step(XG(1,0),XG(1,1),XG(1,2),XG(1,3),XG(1,4), pgg.y, ra, 1);
            step(XG(2,0),XG(2,1),XG(2,2),XG(2,3),XG(2,4), pgg.z, ra, 2);
            step(XG(3,0),XG(3,1),XG(3,2),XG(3,3),XG(3,4), pgg.w, ra, 3);
            __syncwarp();
            issue(g + 3);
            if (g & 1) renorm();
        }
        CP_WAIT(0); __syncwarp();
        #pragma unroll 1
        for (int g = 29; g <= 31; ++g) {
            loadx(g);
            int4 pgg = pb4[g];
            unsigned int ra = myrowbase + (unsigned int)(g & 3) * BUF_BYTES;
            step(XG(0,0),XG(0,1),XG(0,2),XG(0,3),XG(0,4), pgg.x, ra, 0);
            step(XG(1,0),XG(1,1),XG(1,2),XG(1,3),XG(1,4), pgg.y, ra, 1);
            step(XG(2,0),XG(2,1),XG(2,2),XG(2,3),XG(2,4), pgg.z, ra, 2);
            step(XG(3,0),XG(3,1),XG(3,2),XG(3,3),XG(3,4), pgg.w, ra, 3);
            if (g == 29) renorm();
        }

        if (sub == 0) {
            fin[set][pair][0] = p0; fin[set][pair][1] = p1; fin[set][pair][2] = p2;
            fin[set][pair][3] = p3; fin[set][pair][4] = p4;
            fin[set][pair][9]  = C;
            fin[set][pair][10] = emit + initterm + tracc;
            fin[set][pair][11] = __int_as_float(ptp);
        } else {
            fin[set][pair][5] = p0; fin[set][pair][6] = p1;
            fin[set][pair][7] = p2; fin[set][pair][8] = p3;
        }
    } else {
        // ===== backward half: t = 255 .. 128, groups 63..32 =====
        auto bstep = [&](float x0, float x1, float x2, float x3, float x4,
                         int pt, unsigned int rowa, int tt) {
            float y0 = p0 * __expf(x0), y1 = p1 * __expf(x1), y2 = p2 * __expf(x2);
            float y3 = p3 * __expf(x3), y4 = p4 * __expf(x4);
            matvec(y0, y1, y2, y3, y4, p0, p1, p2, p3, p4);
            emit  += lds_f(rowa + (unsigned int)((tt * 9 + pt) * 4));
            tracc += s_tran[pt * 9 + ptp];
            ptp = pt;
        };

        issue(63); issue(62); issue(61);
        CP_WAIT(2); __syncwarp();
        loadx(63);
        int4 pg = pb4[63];
        unsigned int rowa = myrowbase + 3u * BUF_BYTES;
        // init: p = E * exp(x_255) = beta_254
        p0 = (ownbase + 0 < 9) ? __expf(XG(3,0)) : 0.f;
        p1 = (ownbase + 1 < 9) ? __expf(XG(3,1)) : 0.f;
        p2 = (ownbase + 2 < 9) ? __expf(XG(3,2)) : 0.f;
        p3 = (ownbase + 3 < 9) ? __expf(XG(3,3)) : 0.f;
        p4 = (ownbase + 4 < 9) ? __expf(XG(3,4)) : 0.f;
        matvec(p0, p1, p2, p3, p4, p0, p1, p2, p3, p4);
        ptp = pg.w;
        emit = lds_f(rowa + (unsigned int)((3 * 9 + pg.w) * 4));
        bstep(XG(2,0),XG(2,1),XG(2,2),XG(2,3),XG(2,4), pg.z, rowa, 2);
        bstep(XG(1,0),XG(1,1),XG(1,2),XG(1,3),XG(1,4), pg.y, rowa, 1);
        bstep(XG(0,0),XG(0,1),XG(0,2),XG(0,3),XG(0,4), pg.x, rowa, 0);
        __syncwarp();
        issue(60);

        #pragma unroll 1
        for (int g = 62; g >= 35; --g) {
            CP_WAIT(2); __syncwarp();
            loadx(g);
            int4 pgg = pb4[g];
            unsigned int ra = myrowbase + (unsigned int)(g & 3) * BUF_BYTES;
            bstep(XG(3,0),XG(3,1),XG(3,2),XG(3,3),XG(3,4), pgg.w, ra, 3);
            bstep(XG(2,0),XG(2,1),XG(2,2),XG(2,3),XG(2,4), pgg.z, ra, 2);
            bstep(XG(1,0),XG(1,1),XG(1,2),XG(1,3),XG(1,4), pgg.y, ra, 1);
            bstep(XG(0,0),XG(0,1),XG(0,2),XG(0,3),XG(0,4), pgg.x, ra, 0);
            __syncwarp();
            issue(g - 3);
            if ((g & 1) == 0) renorm();
        }
        CP_WAIT(0); __syncwarp();
        #pragma unroll 1
        for (int g = 34; g >= 32; --g) {
            loadx(g);
            int4 pgg = pb4[g];
            unsigned int ra = myrowbase + (unsigned int)(g & 3) * BUF_BYTES;
            bstep(XG(3,0),XG(3,1),XG(3,2),XG(3,3),XG(3,4), pgg.w, ra, 3);
            bstep(XG(2,0),XG(2,1),XG(2,2),XG(2,3),XG(2,4), pgg.z, ra, 2);
            bstep(XG(1,0),XG(1,1),XG(1,2),XG(1,3),XG(1,4), pgg.y, ra, 1);
            bstep(XG(0,0),XG(0,1),XG(0,2),XG(0,3),XG(0,4), pgg.x, ra, 0);
            if (g == 34) renorm();
        }

        if (sub == 0) {
            fin[set][pair][12] = p0; fin[set][pair][13] = p1; fin[set][pair][14] = p2;
            fin[set][pair][15] = p3; fin[set][pair][16] = p4;
            fin[set][pair][21] = C;
            fin[set][pair][22] = emit + tracc;
            fin[set][pair][23] = __int_as_float(ptp);
        } else {
            fin[set][pair][17] = p0; fin[set][pair][18] = p1;
            fin[set][pair][19] = p2; fin[set][pair][20] = p3;
        }
    }
    #undef XG

    __syncthreads();

    // combine: per set, the 16 sub==0 lanes of its forward warp
    if (w == 0 && sub == 0) {
        float dot = 0.f;
        #pragma unroll
        for (int i = 0; i < 9; ++i) dot = fmaf(fin[set][pair][i], fin[set][pair][12 + i], dot);
        float logZ = fin[set][pair][9] + fin[set][pair][21] + __logf(dot);
        int pa = __float_as_int(fin[set][pair][11]);
        int pb = __float_as_int(fin[set][pair][23]);
        float score = fin[set][pair][10] + fin[set][pair][22] + s_tran[pa * 9 + pb];
        out[b] = logZ - score;
    }
}

extern "C" void kernel_launch(void* const* d_in, const int* in_sizes, int n_in,
                              void* d_out, int out_size) {
    (void)in_sizes; (void)n_in; (void)out_size;
    const float* inputs = (const float*)d_in[0];
    const int*   path   = (const int*)d_in[1];
    const float* tran   = (const float*)d_in[2];
    const float* initv  = (const float*)d_in[3];
    float* out = (float*)d_out;

    crf_fwd_kernel<<<BB / BPBLK, 128>>>(inputs, path, tran, initv, out);
}